// round 3
// baseline (speedup 1.0000x reference)
#include <cuda_runtime.h>
#include <cfloat>

// Symmetric squared-Hausdorff per batch with EXACT early-break pruning.
// d^2(p,g) = |p|^2 + (|g|^2 - 2 p.g); work in shifted domain s = |g|^2 - 2p.g,
// add |p|^2 at the end.
//
// K1: per (dir,b): LB = exact min-d^2 of the max-radius outer point (valid
//     lower bound of the answer), shrunk by 1e-5 rel margin.
// K2: every outer point scans inner points (packed f32x2: 3 FFMA2 + 2 FMNMX
//     per 2 evals) and STOPS once its partial min certifies it can't be the
//     argmax (partial s < LB - |p|^2). Argmax point never breaks -> exact.
// K3: combine block maxima.

#define BATCH   16
#define NPTS    4096
#define NPAIRS  (NPTS / 2)          // 2048 packed inner pairs
#define T2      512                 // kernel2 threads
#define PTSBLK  256                 // outer points per kernel2 block (2 lanes/pt)
#define OCH     (NPTS / PTSBLK)     // 16 blocks per (dir,b)
#define HPAIRS  (NPAIRS / 2)        // 1024 pairs per lane-half
#define T1      256

__device__ float g_lb[2][BATCH];
__device__ float g_bmax[2][BATCH][OCH];

typedef unsigned long long u64t;

__device__ __forceinline__ u64t fma2(u64t a, u64t b, u64t c) {
    u64t d;
    asm("fma.rn.f32x2 %0, %1, %2, %3;" : "=l"(d) : "l"(a), "l"(b), "l"(c));
    return d;
}
__device__ __forceinline__ u64t pk(float lo, float hi) {
    u64t d;
    asm("mov.b64 %0, {%1, %2};" : "=l"(d) : "f"(lo), "f"(hi));
    return d;
}
__device__ __forceinline__ float2 upk(u64t v) {
    float2 r;
    asm("mov.b64 {%0, %1}, %2;" : "=f"(r.x), "=f"(r.y) : "l"(v));
    return r;
}

// ---------------- K1: lower bound from max-radius outer point ----------------
__global__ void __launch_bounds__(T1)
hd_lb(const float* __restrict__ preds, const float* __restrict__ gts) {
    const int b = blockIdx.x, dir = blockIdx.y;
    const float* __restrict__ outer = (dir == 0 ? preds : gts) + (size_t)b * NPTS * 3;
    const float* __restrict__ inner = (dir == 0 ? gts : preds) + (size_t)b * NPTS * 3;
    const int tid = threadIdx.x;

    // argmax |p|^2 (deterministic tie-break: lowest index)
    float bestr = -1.0f; int besti = 0;
    for (int i = tid; i < NPTS; i += T1) {
        float x = outer[3*i], y = outer[3*i+1], z = outer[3*i+2];
        float r = fmaf(x, x, fmaf(y, y, z * z));
        if (r > bestr || (r == bestr && i < besti)) { bestr = r; besti = i; }
    }
#pragma unroll
    for (int off = 16; off; off >>= 1) {
        float r2 = __shfl_xor_sync(0xffffffffu, bestr, off);
        int   i2 = __shfl_xor_sync(0xffffffffu, besti, off);
        if (r2 > bestr || (r2 == bestr && i2 < besti)) { bestr = r2; besti = i2; }
    }
    __shared__ float sr[T1/32]; __shared__ int si[T1/32];
    __shared__ int s_pi;
    if ((tid & 31) == 0) { sr[tid>>5] = bestr; si[tid>>5] = besti; }
    __syncthreads();
    if (tid == 0) {
        float r = sr[0]; int i = si[0];
#pragma unroll
        for (int w = 1; w < T1/32; w++)
            if (sr[w] > r || (sr[w] == r && si[w] < i)) { r = sr[w]; i = si[w]; }
        s_pi = i;
    }
    __syncthreads();

    const int pi = s_pi;
    const float px = outer[3*pi], py = outer[3*pi+1], pz = outer[3*pi+2];
    const float rq = fmaf(px, px, fmaf(py, py, pz * pz));

    // exact min d^2 over ALL inner points (same fma formula as K2)
    float mn = FLT_MAX;
    for (int j = tid; j < NPTS; j += T1) {
        float gx = inner[3*j], gy = inner[3*j+1], gz = inner[3*j+2];
        float gw = fmaf(gx, gx, fmaf(gy, gy, gz * gz));
        float t = fmaf(-2.0f * gx, px, gw);
        t = fmaf(-2.0f * gy, py, t);
        t = fmaf(-2.0f * gz, pz, t);
        mn = fminf(mn, t);
    }
#pragma unroll
    for (int off = 16; off; off >>= 1)
        mn = fminf(mn, __shfl_xor_sync(0xffffffffu, mn, off));
    __shared__ float sm[T1/32];
    if ((tid & 31) == 0) sm[tid>>5] = mn;
    __syncthreads();
    if (tid == 0) {
        float m = sm[0];
#pragma unroll
        for (int w = 1; w < T1/32; w++) m = fminf(m, sm[w]);
        float lb = m + rq;                       // valid LB of the answer
        // safety margin against rounding-order differences (exactness margin)
        g_lb[dir][b] = lb - fabsf(lb) * 1e-5f - 1e-12f;
    }
}

// ---------------- K2: early-exit scan ----------------
__global__ void __launch_bounds__(T2)
hd_main(const float* __restrict__ preds, const float* __restrict__ gts) {
    extern __shared__ __align__(16) ulonglong2 shv[];   // NPAIRS*2 = 64 KB

    const int och = blockIdx.x, b = blockIdx.y, dir = blockIdx.z;
    const float* __restrict__ outer = (dir == 0 ? preds : gts) + (size_t)b * NPTS * 3;
    const float* __restrict__ inner = (dir == 0 ? gts : preds) + (size_t)b * NPTS * 3;
    const int tid = threadIdx.x;

    // stage inner points, fused packed-pair format:
    // pair pj -> {-2x0,-2x1},{-2y0,-2y1},{-2z0,-2z1},{w0,w1}
    {
        float* shf = (float*)shv;
        for (int pj = tid; pj < NPAIRS; pj += T2) {
            const float* gp = inner + (size_t)pj * 6;
            float x0 = gp[0], y0 = gp[1], z0 = gp[2];
            float x1 = gp[3], y1 = gp[4], z1 = gp[5];
            shf[pj*8+0] = -2.0f*x0;  shf[pj*8+1] = -2.0f*x1;
            shf[pj*8+2] = -2.0f*y0;  shf[pj*8+3] = -2.0f*y1;
            shf[pj*8+4] = -2.0f*z0;  shf[pj*8+5] = -2.0f*z1;
            shf[pj*8+6] = fmaf(x0, x0, fmaf(y0, y0, z0*z0));
            shf[pj*8+7] = fmaf(x1, x1, fmaf(y1, y1, z1*z1));
        }
    }
    __syncthreads();

    // two lanes per outer point: lane half scans pairs [half*HPAIRS, +HPAIRS)
    const int p_idx = och * PTSBLK + (tid >> 1);
    const int half  = tid & 1;
    const float x = outer[3*p_idx], y = outer[3*p_idx+1], z = outer[3*p_idx+2];
    const float rq = fmaf(x, x, fmaf(y, y, z * z));
    const u64t px2 = pk(x, x), py2 = pk(y, y), pz2 = pk(z, z);
    const float lbs = g_lb[dir][b] - rq;        // break threshold, shifted domain

    float mnA = FLT_MAX, mnB = FLT_MAX;
    const int j0 = half * HPAIRS;
    for (int jp = j0; jp < j0 + HPAIRS; jp += 4) {
        // 4 packed pairs = 8 evals; two independent min chains
#pragma unroll
        for (int c = 0; c < 2; c++) {
            ulonglong2 ab = shv[(jp + c) * 2 + 0];
            ulonglong2 cd = shv[(jp + c) * 2 + 1];
            u64t t = fma2(ab.x, px2, cd.y);
            t = fma2(ab.y, py2, t);
            t = fma2(cd.x, pz2, t);
            float2 tv = upk(t);
            mnA = fminf(mnA, fminf(tv.x, tv.y));
        }
#pragma unroll
        for (int c = 2; c < 4; c++) {
            ulonglong2 ab = shv[(jp + c) * 2 + 0];
            ulonglong2 cd = shv[(jp + c) * 2 + 1];
            u64t t = fma2(ab.x, px2, cd.y);
            t = fma2(ab.y, py2, t);
            t = fma2(cd.x, pz2, t);
            float2 tv = upk(t);
            mnB = fminf(mnB, fminf(tv.x, tv.y));
        }
        if (fminf(mnA, mnB) < lbs) break;       // certified non-argmax: stop
    }

    float mn = fminf(mnA, mnB);
    mn = fminf(mn, __shfl_xor_sync(0xffffffffu, mn, 1));   // join the two halves
    float v = mn + rq;                                      // candidate min d^2

    // block max reduce
#pragma unroll
    for (int off = 16; off; off >>= 1)
        v = fmaxf(v, __shfl_xor_sync(0xffffffffu, v, off));
    __shared__ float wm[T2/32];
    if ((tid & 31) == 0) wm[tid>>5] = v;
    __syncthreads();
    if (tid == 0) {
        float m = wm[0];
#pragma unroll
        for (int w = 1; w < T2/32; w++) m = fmaxf(m, wm[w]);
        g_bmax[dir][b][och] = m;
    }
}

// ---------------- K3: combine ----------------
__global__ void hd_combine(float* __restrict__ out) {
    const int b = blockIdx.x, tid = threadIdx.x;   // 32 threads
    float v0 = (tid < OCH) ? g_bmax[0][b][tid] : -FLT_MAX;
    float v1 = (tid < OCH) ? g_bmax[1][b][tid] : -FLT_MAX;
#pragma unroll
    for (int off = 16; off; off >>= 1) {
        v0 = fmaxf(v0, __shfl_xor_sync(0xffffffffu, v0, off));
        v1 = fmaxf(v1, __shfl_xor_sync(0xffffffffu, v1, off));
    }
    if (tid == 0) out[b] = 0.5f * (v0 + v1);
}

extern "C" void kernel_launch(void* const* d_in, const int* in_sizes, int n_in,
                              void* d_out, int out_size) {
    const float* preds = (const float*)d_in[0];
    const float* gts   = (const float*)d_in[1];
    float* out = (float*)d_out;

    const int smem = NPAIRS * 2 * sizeof(ulonglong2);   // 64 KB
    cudaFuncSetAttribute(hd_main,
                         cudaFuncAttributeMaxDynamicSharedMemorySize, smem);

    hd_lb<<<dim3(BATCH, 2), T1>>>(preds, gts);
    hd_main<<<dim3(OCH, BATCH, 2), T2, smem>>>(preds, gts);
    hd_combine<<<BATCH, 32>>>(out);
}